// round 14
// baseline (speedup 1.0000x reference)
#include <cuda_runtime.h>
#include <cuda_bf16.h>
#include <cstdint>

#define BSZ 128
#define DIM 1024
#define NCLS 32768
#define INV_TAU 20.0f
#define THRESH 20.0f
#define BN 256
#define NBLK (NCLS / BN)    // 128 gemm blocks (one wave)
#define BK 32               // k per tile (32 fp8 bytes per row)
#define NT (DIM / BK)       // 32 iterations

#define NCONS 512           // 16 consumer warps
#define NPROD 128           // 4 producer warps
#define NTHREADS 640
#define NSLOT 4

// Scratch (device globals: no allocations allowed)
__device__ alignas(16) uint8_t g_a8[BSZ * DIM];         // e4m3 inputs
__device__ alignas(16) float g_pse[BSZ * NBLK];         // partial sumexp(s-20)
__device__ alignas(16) float g_pcn[BSZ * NBLK];         // partial count > 20
__device__ alignas(16) float g_pss[BSZ * NBLK];         // partial sum of s > 20
__device__ alignas(16) float g_st[BSZ];                 // s[target[b]]

// dynamic smem rings (4 slots each):
//   A fp8   : 128 rows x 48B stride  = 6144/slot   @ 0
//   B fp8   : 256 rows x 48B stride  = 12288/slot  @ 24576
//   B fp32  : 256 rows x 128B        = 32768/slot  @ 73728
#define A_OFF 0
#define B8_OFF 24576
#define BF32_OFF 73728
#define SMEM_DYN 204800
#define RSTRIDE 48

// named barriers: 1+s = FULL(s), 5+s = EMPTY(s)
#define BAR_FULL(s) (1 + (s))
#define BAR_EMPTY(s) (5 + (s))

__device__ __forceinline__ void bar_sync(int id) {
    asm volatile("bar.sync %0, %1;" :: "r"(id), "n"(NTHREADS) : "memory");
}
__device__ __forceinline__ void bar_arrive(int id) {
    asm volatile("bar.arrive %0, %1;" :: "r"(id), "n"(NTHREADS) : "memory");
}
__device__ __forceinline__ unsigned su32(const void* p) {
    return (unsigned)__cvta_generic_to_shared(p);
}
__device__ __forceinline__ uint32_t pack_e4m3x4(float4 v) {
    uint16_t lo, hi;
    asm("cvt.rn.satfinite.e4m3x2.f32 %0, %1, %2;" : "=h"(lo) : "f"(v.y), "f"(v.x));
    asm("cvt.rn.satfinite.e4m3x2.f32 %0, %1, %2;" : "=h"(hi) : "f"(v.w), "f"(v.z));
    return (uint32_t)lo | ((uint32_t)hi << 16);
}
__device__ __forceinline__ void cpasync16(uint32_t dst, const void* src) {
    asm volatile("cp.async.cg.shared.global [%0], [%1], 16;"
                 :: "r"(dst), "l"(src) : "memory");
}
__device__ __forceinline__ void mma_fp8(float* c, const uint32_t* a, const uint32_t* b) {
    asm volatile(
        "mma.sync.aligned.m16n8k32.row.col.f32.e4m3.e4m3.f32 "
        "{%0,%1,%2,%3}, {%4,%5,%6,%7}, {%8,%9}, {%0,%1,%2,%3};\n"
        : "+f"(c[0]), "+f"(c[1]), "+f"(c[2]), "+f"(c[3])
        : "r"(a[0]), "r"(a[1]), "r"(a[2]), "r"(a[3]), "r"(b[0]), "r"(b[1]));
}

// ---------------------------------------------------------------------------
// K0: convert inputs to e4m3 once
// ---------------------------------------------------------------------------
__global__ __launch_bounds__(256) void convert_inputs_kernel(const float* __restrict__ in) {
    int i = (blockIdx.x * 256 + threadIdx.x) * 4;
    float4 v = *reinterpret_cast<const float4*>(&in[i]);
    *reinterpret_cast<uint32_t*>(&g_a8[i]) = pack_e4m3x4(v);
}

// ---------------------------------------------------------------------------
// K1: warp-specialized fp8 GEMM (scores = inputs @ em^T * 20) fused with
// em -> out_em copy and softmax statistics.
//   warps 0..15  : consumers — ldmatrix + QMMA only (32x64 tile each);
//                  EMPTY released right after ldmatrix (frags in regs)
//   warps 16..19 : producers — cp.async rings, out_em copy, fp8 staging
// 4-slot rings; named-barrier full/empty handshake; wait_group 3.
// ---------------------------------------------------------------------------
__global__ __launch_bounds__(NTHREADS, 1) void gemm_fused_kernel(
    const float* __restrict__ em,
    float* __restrict__ out_em,
    const int* __restrict__ targets) {
    extern __shared__ char dsm[];
    __shared__ float sRed[3][BSZ][4];
    __shared__ int sT[BSZ];

    const int tid = threadIdx.x;
    const int warp = tid >> 5;
    const int lane = tid & 31;
    const int cBase = blockIdx.x * BN;

    if (tid < BSZ) sT[tid] = targets[tid];
    __syncthreads();

    if (warp >= 16) {
        // =================== PRODUCER ===================
        const int p = tid - NCONS;  // 0..127

        auto issueTile = [&](int t) {
            const int slot = t % NSLOT;
            char* bdst = dsm + BF32_OFF + slot * 32768;
#pragma unroll
            for (int j = 0; j < 16; j++) {
                int c = p + j * 128;          // 0..2047
                int row = c >> 3, q = c & 7;
                cpasync16(su32(bdst + row * 128 + q * 16),
                          (const char*)em +
                              ((size_t)(cBase + row) * DIM + t * BK + q * 4) * 4);
            }
            char* adst = dsm + A_OFF + slot * 6144;
#pragma unroll
            for (int h2 = 0; h2 < 2; h2++) {
                int c = p + h2 * 128;         // 0..255
                int row = c >> 1, h = c & 1;
                cpasync16(su32(adst + row * RSTRIDE + h * 16),
                          (const char*)g_a8 + row * DIM + t * BK + h * 16);
            }
        };

        issueTile(0);
        asm volatile("cp.async.commit_group;" ::: "memory");
        issueTile(1);
        asm volatile("cp.async.commit_group;" ::: "memory");
        issueTile(2);
        asm volatile("cp.async.commit_group;" ::: "memory");

        for (int kt = 0; kt < NT; kt++) {
            const int t = kt + 3;
            if (t < NT) {
                if (t >= NSLOT) bar_sync(BAR_EMPTY(t % NSLOT));  // slot freed
                issueTile(t);
            }
            asm volatile("cp.async.commit_group;" ::: "memory");
            asm volatile("cp.async.wait_group 3;" ::: "memory");  // tile kt landed

            // ---- stage tile kt: fp32 ring -> out_em copy + fp8 ring ----
            const int slot = kt % NSLOT;
            const char* bsrc = dsm + BF32_OFF + slot * 32768;
            char* b8 = dsm + B8_OFF + slot * 12288;
#pragma unroll
            for (int j = 0; j < 16; j++) {
                int c = p + j * 128;
                int row = c >> 3, q = c & 7;
                float4 v = *reinterpret_cast<const float4*>(bsrc + row * 128 + q * 16);
                size_t gb = (size_t)(cBase + row) * DIM + kt * BK + q * 4;
                __stcs(&out_em[gb], v.x);                              // addr 4 mod 16
                __stcs(reinterpret_cast<float2*>(&out_em[gb + 1]),
                       make_float2(v.y, v.z));                         // addr 8 mod 16
                __stcs(&out_em[gb + 3], v.w);
                *reinterpret_cast<uint32_t*>(b8 + row * RSTRIDE + q * 4) = pack_e4m3x4(v);
            }
            bar_arrive(BAR_FULL(slot));
        }
    } else {
        // =================== CONSUMER ===================
        const int wR = warp & 3;   // M row-group (32 rows)
        const int wC = warp >> 2;  // N col-group (64 cols)

        float acc[2][8][4];
#pragma unroll
        for (int i = 0; i < 2; i++)
#pragma unroll
            for (int j = 0; j < 8; j++)
#pragma unroll
                for (int k = 0; k < 4; k++) acc[i][j][k] = 0.0f;

        const int ar = lane & 15;
        const int ah = (lane >> 4) * 16;
        const int br = lane & 7;
        const int bh = ((lane >> 3) & 1) * 16;

        for (int kt = 0; kt < NT; kt++) {
            const int slot = kt % NSLOT;
            bar_sync(BAR_FULL(slot));
            const char* as = dsm + A_OFF + slot * 6144;
            const char* bs = dsm + B8_OFF + slot * 12288;

            uint32_t afr[2][4];
#pragma unroll
            for (int i = 0; i < 2; i++) {
                unsigned addr = su32(as + (wR * 32 + i * 16 + ar) * RSTRIDE + ah);
                asm volatile(
                    "ldmatrix.sync.aligned.m8n8.x4.shared.b16 {%0,%1,%2,%3}, [%4];"
                    : "=r"(afr[i][0]), "=r"(afr[i][1]), "=r"(afr[i][2]), "=r"(afr[i][3])
                    : "r"(addr));
            }
            uint32_t bfr[8][2];
#pragma unroll
            for (int j = 0; j < 8; j++) {
                unsigned addr = su32(bs + (wC * 64 + j * 8 + br) * RSTRIDE + bh);
                asm volatile(
                    "ldmatrix.sync.aligned.m8n8.x2.shared.b16 {%0,%1}, [%2];"
                    : "=r"(bfr[j][0]), "=r"(bfr[j][1])
                    : "r"(addr));
            }
            bar_arrive(BAR_EMPTY(slot));  // frags in regs: free slot BEFORE mma

#pragma unroll
            for (int j = 0; j < 8; j++) {
                mma_fp8(acc[0][j], afr[0], bfr[j]);
                mma_fp8(acc[1][j], afr[1], bfr[j]);
            }
        }

        // ---- fused epilogue: per-row partial statistics ----
#pragma unroll
        for (int i = 0; i < 2; i++) {
#pragma unroll
            for (int half = 0; half < 2; half++) {
                int bb = wR * 32 + i * 16 + (lane >> 2) + half * 8;  // sample index
                int tgt = sT[bb];
                float se = 0.0f, cn = 0.0f, ss = 0.0f;
#pragma unroll
                for (int j = 0; j < 8; j++) {
                    int cc = cBase + wC * 64 + j * 8 + (lane & 3) * 2;
                    float v0 = acc[i][j][half * 2 + 0] * INV_TAU;
                    float v1 = acc[i][j][half * 2 + 1] * INV_TAU;
                    se += __expf(v0 - 20.0f) + __expf(v1 - 20.0f);
                    if (v0 > THRESH) { cn += 1.0f; ss += v0; }
                    if (v1 > THRESH) { cn += 1.0f; ss += v1; }
                    if (cc == tgt) g_st[bb] = v0;
                    if (cc + 1 == tgt) g_st[bb] = v1;
                }
#pragma unroll
                for (int o = 1; o < 4; o <<= 1) {
                    se += __shfl_xor_sync(~0u, se, o);
                    cn += __shfl_xor_sync(~0u, cn, o);
                    ss += __shfl_xor_sync(~0u, ss, o);
                }
                if ((lane & 3) == 0) {
                    sRed[0][bb][wC] = se;
                    sRed[1][bb][wC] = cn;
                    sRed[2][bb][wC] = ss;
                }
            }
        }
    }

    __syncthreads();
    if (tid < BSZ) {
        g_pse[tid * NBLK + blockIdx.x] =
            sRed[0][tid][0] + sRed[0][tid][1] + sRed[0][tid][2] + sRed[0][tid][3];
        g_pcn[tid * NBLK + blockIdx.x] =
            sRed[1][tid][0] + sRed[1][tid][1] + sRed[1][tid][2] + sRed[1][tid][3];
        g_pss[tid * NBLK + blockIdx.x] =
            sRed[2][tid][0] + sRed[2][tid][1] + sRed[2][tid][2] + sRed[2][tid][3];
    }
}

// ---------------------------------------------------------------------------
// K2: fused scatter + loss.
// Blocks 0..127: EMA scatter chains (O(1) head detection via smem + ballot).
// Block 128: reduce partials, write ks and final loss mean.
// ---------------------------------------------------------------------------
__global__ __launch_bounds__(256) void scatter_loss_kernel(const float* __restrict__ inputs,
                                                           const int* __restrict__ targets,
                                                           const int* __restrict__ epoch,
                                                           float* __restrict__ out_em,
                                                           float* __restrict__ out) {
    const int t = threadIdx.x;
    const int warp = t >> 5;
    const int lane = t & 31;

    if (blockIdx.x == BSZ) {
        __shared__ float sLoss[BSZ];
        for (int b = warp; b < BSZ; b += 8) {
            float se = 0.0f, cn = 0.0f, ss = 0.0f;
#pragma unroll
            for (int i = lane; i < NBLK; i += 32) {
                se += g_pse[b * NBLK + i];
                cn += g_pcn[b * NBLK + i];
                ss += g_pss[b * NBLK + i];
            }
#pragma unroll
            for (int o = 16; o; o >>= 1) {
                se += __shfl_xor_sync(~0u, se, o);
                cn += __shfl_xor_sync(~0u, cn, o);
                ss += __shfl_xor_sync(~0u, ss, o);
            }
            if (lane == 0) {
                float st = g_st[b];
                float lse = 20.0f + logf(se);
                float logpt = st - lse;
                int n = (int)(cn + 0.5f);
                float loss;
                if (n > 1) {
                    float kk = 1.0f / ((float)n * logf((float)n));
                    int ta = (st > THRESH) ? 1 : 0;
                    float extra = kk * ((ss - (ta ? st : 0.0f)) - (float)(n - ta) * lse);
                    loss = -(extra + logpt);
                } else {
                    loss = -logpt;
                }
                sLoss[b] = loss;
                out[1 + b] = cn;  // ks
            }
        }
        __syncthreads();
        if (t == 0) {
            float acc = 0.0f;
            for (int i = 0; i < BSZ; i++) acc += sLoss[i];
            out[0] = acc / (float)BSZ;
        }
        return;
    }

    // ---- scatter block ----
    __shared__ int sT[BSZ];
    __shared__ float red[8];
    __shared__ float bc;
    if (t < BSZ) sT[t] = targets[t];
    __syncthreads();

    const int b = blockIdx.x;
    const int y = sT[b];
    int match = (t < b && sT[t] == y) ? 1 : 0;
    if (__syncthreads_or(match)) return;  // not the chain head (uniform)

    const float mu = fminf(0.4f / 60.0f * (float)(epoch[0] + 1), 1.0f);
    const float omu = 1.0f - mu;

    const size_t rbase = (size_t)y * DIM + t * 4;
    float row[4];
#pragma unroll
    for (int q = 0; q < 4; q++) row[q] = out_em[rbase + q];  // scalar: base 4 mod 16

    for (int j = b; j < BSZ; j++) {
        if (sT[j] != y) continue;  // uniform across block (smem)
        float4 x = *reinterpret_cast<const float4*>(&inputs[(size_t)j * DIM + t * 4]);
        float v0 = mu * row[0] + omu * x.x;
        float v1 = mu * row[1] + omu * x.y;
        float v2 = mu * row[2] + omu * x.z;
        float v3 = mu * row[3] + omu * x.w;
        float sq = v0 * v0 + v1 * v1 + v2 * v2 + v3 * v3;
#pragma unroll
        for (int o = 16; o; o >>= 1) sq += __shfl_xor_sync(~0u, sq, o);
        if (lane == 0) red[warp] = sq;
        __syncthreads();
        if (t == 0) {
            float s = 0.0f;
#pragma unroll
            for (int i = 0; i < 8; i++) s += red[i];
            bc = s;
        }
        __syncthreads();
        float rn = rsqrtf(bc);
        row[0] = v0 * rn; row[1] = v1 * rn; row[2] = v2 * rn; row[3] = v3 * rn;
    }
#pragma unroll
    for (int q = 0; q < 4; q++) out_em[rbase + q] = row[q];
}

// ---------------------------------------------------------------------------
// Entry point. Output layout (float32): [loss(1), ks(128), new_em(32768*1024)]
// ---------------------------------------------------------------------------
extern "C" void kernel_launch(void* const* d_in, const int* in_sizes, int n_in,
                              void* d_out, int out_size) {
    const float* inputs = (const float*)d_in[0];
    const float* em = (const float*)d_in[1];
    const int* targets = (const int*)d_in[2];
    const int* epoch = (const int*)d_in[3];
    float* out = (float*)d_out;
    float* out_em = out + 1 + BSZ;

    static bool attr_set = false;
    if (!attr_set) {
        cudaFuncSetAttribute(gemm_fused_kernel,
                             cudaFuncAttributeMaxDynamicSharedMemorySize, SMEM_DYN);
        attr_set = true;
    }

    convert_inputs_kernel<<<128, 256>>>(inputs);
    gemm_fused_kernel<<<NBLK, NTHREADS, SMEM_DYN>>>(em, out_em, targets);
    scatter_loss_kernel<<<BSZ + 1, 256>>>(inputs, targets, epoch, out_em, out);
}

// round 15
// speedup vs baseline: 1.2532x; 1.2532x over previous
#include <cuda_runtime.h>
#include <cuda_bf16.h>
#include <cstdint>

#define BSZ 128
#define DIM 1024
#define NCLS 32768
#define INV_TAU 20.0f
#define THRESH 20.0f
#define BN 256
#define NBLK (NCLS / BN)    // 128 gemm blocks (one wave)
#define BK 32               // k per tile (32 fp8 bytes / 32 floats per row)
#define NT (DIM / BK)       // 32 iterations

#define NCONS 512           // 16 consumer warps
#define NTHREADS 640        // + 4 producer warps
#define NSLOT 3

// Scratch (device globals: no allocations allowed)
__device__ alignas(16) float g_pse[BSZ * NBLK];         // partial sumexp(s-20)
__device__ alignas(16) float g_pcn[BSZ * NBLK];         // partial count > 20
__device__ alignas(16) float g_pss[BSZ * NBLK];         // partial sum of s > 20
__device__ alignas(16) float g_st[BSZ];                 // s[target[b]]

// dynamic smem rings (3 slots each):
//   A fp8   : 128 rows x 48B stride  = 6144/slot   @ 0
//   B fp8   : 256 rows x 48B stride  = 12288/slot  @ 18432
//   A fp32  : 128 rows x 128B        = 16384/slot  @ 55296
//   B fp32  : 256 rows x 128B        = 32768/slot  @ 104448
#define A8_OFF 0
#define B8_OFF 18432
#define A32_OFF 55296
#define B32_OFF 104448
#define SMEM_DYN 202752
#define RSTRIDE 48

// named barriers: 1+s = FULL(s), 4+s = EMPTY(s)
#define BAR_FULL(s) (1 + (s))
#define BAR_EMPTY(s) (4 + (s))

__device__ __forceinline__ void bar_sync(int id) {
    asm volatile("bar.sync %0, %1;" :: "r"(id), "n"(NTHREADS) : "memory");
}
__device__ __forceinline__ void bar_arrive(int id) {
    asm volatile("bar.arrive %0, %1;" :: "r"(id), "n"(NTHREADS) : "memory");
}
__device__ __forceinline__ unsigned su32(const void* p) {
    return (unsigned)__cvta_generic_to_shared(p);
}
__device__ __forceinline__ uint32_t pack_e4m3x4(float4 v) {
    uint16_t lo, hi;
    asm("cvt.rn.satfinite.e4m3x2.f32 %0, %1, %2;" : "=h"(lo) : "f"(v.y), "f"(v.x));
    asm("cvt.rn.satfinite.e4m3x2.f32 %0, %1, %2;" : "=h"(hi) : "f"(v.w), "f"(v.z));
    return (uint32_t)lo | ((uint32_t)hi << 16);
}
__device__ __forceinline__ void cpasync16(uint32_t dst, const void* src) {
    asm volatile("cp.async.cg.shared.global [%0], [%1], 16;"
                 :: "r"(dst), "l"(src) : "memory");
}
__device__ __forceinline__ void mma_fp8(float* c, const uint32_t* a, const uint32_t* b) {
    asm volatile(
        "mma.sync.aligned.m16n8k32.row.col.f32.e4m3.e4m3.f32 "
        "{%0,%1,%2,%3}, {%4,%5,%6,%7}, {%8,%9}, {%0,%1,%2,%3};\n"
        : "+f"(c[0]), "+f"(c[1]), "+f"(c[2]), "+f"(c[3])
        : "r"(a[0]), "r"(a[1]), "r"(a[2]), "r"(a[3]), "r"(b[0]), "r"(b[1]));
}

// ---------------------------------------------------------------------------
// K1: warp-specialized fp8 GEMM (scores = inputs @ em^T * 20) fused with
// em -> out_em copy, inputs fp32 -> fp8 conversion, and softmax statistics.
//   warps 0..15  : consumers — ldmatrix + QMMA only (32x64 tile each)
//   warps 16..19 : producers — cp.async rings (A fp32 + B fp32), out_em copy,
//                  fp8 staging of both operands
// 3-slot rings; named-barrier full/empty handshake; wait_group 2. (R12 base)
// ---------------------------------------------------------------------------
__global__ __launch_bounds__(NTHREADS, 1) void gemm_fused_kernel(
    const float* __restrict__ inputs,
    const float* __restrict__ em,
    float* __restrict__ out_em,
    const int* __restrict__ targets) {
    extern __shared__ char dsm[];
    __shared__ float sRed[3][BSZ][4];
    __shared__ int sT[BSZ];

    const int tid = threadIdx.x;
    const int warp = tid >> 5;
    const int lane = tid & 31;
    const int cBase = blockIdx.x * BN;

    if (tid < BSZ) sT[tid] = targets[tid];
    __syncthreads();

    if (warp >= 16) {
        // =================== PRODUCER ===================
        const int p = tid - NCONS;  // 0..127

        auto issueTile = [&](int t) {
            const int slot = t % NSLOT;
            char* bdst = dsm + B32_OFF + slot * 32768;
#pragma unroll
            for (int j = 0; j < 16; j++) {
                int c = p + j * 128;          // 0..2047
                int row = c >> 3, q = c & 7;
                cpasync16(su32(bdst + row * 128 + q * 16),
                          (const char*)em +
                              ((size_t)(cBase + row) * DIM + t * BK + q * 4) * 4);
            }
            char* adst = dsm + A32_OFF + slot * 16384;
#pragma unroll
            for (int j = 0; j < 8; j++) {
                int c = p + j * 128;          // 0..1023
                int row = c >> 3, q = c & 7;
                cpasync16(su32(adst + row * 128 + q * 16),
                          (const char*)inputs +
                              ((size_t)row * DIM + t * BK + q * 4) * 4);
            }
        };

        issueTile(0);
        asm volatile("cp.async.commit_group;" ::: "memory");
        issueTile(1);
        asm volatile("cp.async.commit_group;" ::: "memory");

        for (int kt = 0; kt < NT; kt++) {
            const int t = kt + 2;
            if (t < NT) {
                if (t >= NSLOT) bar_sync(BAR_EMPTY(t % NSLOT));  // slot freed
                issueTile(t);
            }
            asm volatile("cp.async.commit_group;" ::: "memory");
            asm volatile("cp.async.wait_group 2;" ::: "memory");  // tile kt landed

            const int slot = kt % NSLOT;
            // ---- stage B tile kt: fp32 ring -> out_em copy + fp8 ring ----
            {
                const char* bsrc = dsm + B32_OFF + slot * 32768;
                char* b8 = dsm + B8_OFF + slot * 12288;
#pragma unroll
                for (int j = 0; j < 16; j++) {
                    int c = p + j * 128;
                    int row = c >> 3, q = c & 7;
                    float4 v = *reinterpret_cast<const float4*>(bsrc + row * 128 + q * 16);
                    size_t gb = (size_t)(cBase + row) * DIM + kt * BK + q * 4;
                    __stcs(&out_em[gb], v.x);                              // addr 4 mod 16
                    __stcs(reinterpret_cast<float2*>(&out_em[gb + 1]),
                           make_float2(v.y, v.z));                         // addr 8 mod 16
                    __stcs(&out_em[gb + 3], v.w);
                    *reinterpret_cast<uint32_t*>(b8 + row * RSTRIDE + q * 4) =
                        pack_e4m3x4(v);
                }
            }
            // ---- stage A tile kt: fp32 ring -> fp8 ring ----
            {
                const char* asrc = dsm + A32_OFF + slot * 16384;
                char* a8 = dsm + A8_OFF + slot * 6144;
#pragma unroll
                for (int j = 0; j < 8; j++) {
                    int c = p + j * 128;
                    int row = c >> 3, q = c & 7;
                    float4 v = *reinterpret_cast<const float4*>(asrc + row * 128 + q * 16);
                    *reinterpret_cast<uint32_t*>(a8 + row * RSTRIDE + q * 4) =
                        pack_e4m3x4(v);
                }
            }
            bar_arrive(BAR_FULL(slot));
        }
    } else {
        // =================== CONSUMER ===================
        const int wR = warp & 3;   // M row-group (32 rows)
        const int wC = warp >> 2;  // N col-group (64 cols)

        float acc[2][8][4];
#pragma unroll
        for (int i = 0; i < 2; i++)
#pragma unroll
            for (int j = 0; j < 8; j++)
#pragma unroll
                for (int k = 0; k < 4; k++) acc[i][j][k] = 0.0f;

        const int ar = lane & 15;
        const int ah = (lane >> 4) * 16;
        const int br = lane & 7;
        const int bh = ((lane >> 3) & 1) * 16;

        for (int kt = 0; kt < NT; kt++) {
            const int slot = kt % NSLOT;
            bar_sync(BAR_FULL(slot));
            const char* as = dsm + A8_OFF + slot * 6144;
            const char* bs = dsm + B8_OFF + slot * 12288;

            uint32_t afr[2][4];
#pragma unroll
            for (int i = 0; i < 2; i++) {
                unsigned addr = su32(as + (wR * 32 + i * 16 + ar) * RSTRIDE + ah);
                asm volatile(
                    "ldmatrix.sync.aligned.m8n8.x4.shared.b16 {%0,%1,%2,%3}, [%4];"
                    : "=r"(afr[i][0]), "=r"(afr[i][1]), "=r"(afr[i][2]), "=r"(afr[i][3])
                    : "r"(addr));
            }
#pragma unroll
            for (int j = 0; j < 8; j++) {
                uint32_t bfr[2];
                unsigned addr = su32(bs + (wC * 64 + j * 8 + br) * RSTRIDE + bh);
                asm volatile(
                    "ldmatrix.sync.aligned.m8n8.x2.shared.b16 {%0,%1}, [%2];"
                    : "=r"(bfr[0]), "=r"(bfr[1])
                    : "r"(addr));
                mma_fp8(acc[0][j], afr[0], bfr);
                mma_fp8(acc[1][j], afr[1], bfr);
            }
            bar_arrive(BAR_EMPTY(slot));
        }

        // ---- fused epilogue: per-row partial statistics ----
#pragma unroll
        for (int i = 0; i < 2; i++) {
#pragma unroll
            for (int half = 0; half < 2; half++) {
                int bb = wR * 32 + i * 16 + (lane >> 2) + half * 8;  // sample index
                int tgt = sT[bb];
                float se = 0.0f, cn = 0.0f, ss = 0.0f;
#pragma unroll
                for (int j = 0; j < 8; j++) {
                    int cc = cBase + wC * 64 + j * 8 + (lane & 3) * 2;
                    float v0 = acc[i][j][half * 2 + 0] * INV_TAU;
                    float v1 = acc[i][j][half * 2 + 1] * INV_TAU;
                    se += __expf(v0 - 20.0f) + __expf(v1 - 20.0f);
                    if (v0 > THRESH) { cn += 1.0f; ss += v0; }
                    if (v1 > THRESH) { cn += 1.0f; ss += v1; }
                    if (cc == tgt) g_st[bb] = v0;
                    if (cc + 1 == tgt) g_st[bb] = v1;
                }
#pragma unroll
                for (int o = 1; o < 4; o <<= 1) {
                    se += __shfl_xor_sync(~0u, se, o);
                    cn += __shfl_xor_sync(~0u, cn, o);
                    ss += __shfl_xor_sync(~0u, ss, o);
                }
                if ((lane & 3) == 0) {
                    sRed[0][bb][wC] = se;
                    sRed[1][bb][wC] = cn;
                    sRed[2][bb][wC] = ss;
                }
            }
        }
    }

    __syncthreads();
    if (tid < BSZ) {
        g_pse[tid * NBLK + blockIdx.x] =
            sRed[0][tid][0] + sRed[0][tid][1] + sRed[0][tid][2] + sRed[0][tid][3];
        g_pcn[tid * NBLK + blockIdx.x] =
            sRed[1][tid][0] + sRed[1][tid][1] + sRed[1][tid][2] + sRed[1][tid][3];
        g_pss[tid * NBLK + blockIdx.x] =
            sRed[2][tid][0] + sRed[2][tid][1] + sRed[2][tid][2] + sRed[2][tid][3];
    }
}

// ---------------------------------------------------------------------------
// K2: fused scatter + loss.
// Blocks 0..127: EMA scatter chains (O(1) head detection via smem + ballot).
// Block 128: reduce partials, write ks and final loss mean.
// ---------------------------------------------------------------------------
__global__ __launch_bounds__(256) void scatter_loss_kernel(const float* __restrict__ inputs,
                                                           const int* __restrict__ targets,
                                                           const int* __restrict__ epoch,
                                                           float* __restrict__ out_em,
                                                           float* __restrict__ out) {
    const int t = threadIdx.x;
    const int warp = t >> 5;
    const int lane = t & 31;

    if (blockIdx.x == BSZ) {
        __shared__ float sLoss[BSZ];
        for (int b = warp; b < BSZ; b += 8) {
            float se = 0.0f, cn = 0.0f, ss = 0.0f;
#pragma unroll
            for (int i = lane; i < NBLK; i += 32) {
                se += g_pse[b * NBLK + i];
                cn += g_pcn[b * NBLK + i];
                ss += g_pss[b * NBLK + i];
            }
#pragma unroll
            for (int o = 16; o; o >>= 1) {
                se += __shfl_xor_sync(~0u, se, o);
                cn += __shfl_xor_sync(~0u, cn, o);
                ss += __shfl_xor_sync(~0u, ss, o);
            }
            if (lane == 0) {
                float st = g_st[b];
                float lse = 20.0f + logf(se);
                float logpt = st - lse;
                int n = (int)(cn + 0.5f);
                float loss;
                if (n > 1) {
                    float kk = 1.0f / ((float)n * logf((float)n));
                    int ta = (st > THRESH) ? 1 : 0;
                    float extra = kk * ((ss - (ta ? st : 0.0f)) - (float)(n - ta) * lse);
                    loss = -(extra + logpt);
                } else {
                    loss = -logpt;
                }
                sLoss[b] = loss;
                out[1 + b] = cn;  // ks
            }
        }
        __syncthreads();
        if (t == 0) {
            float acc = 0.0f;
            for (int i = 0; i < BSZ; i++) acc += sLoss[i];
            out[0] = acc / (float)BSZ;
        }
        return;
    }

    // ---- scatter block ----
    __shared__ int sT[BSZ];
    __shared__ float red[8];
    __shared__ float bc;
    if (t < BSZ) sT[t] = targets[t];
    __syncthreads();

    const int b = blockIdx.x;
    const int y = sT[b];
    int match = (t < b && sT[t] == y) ? 1 : 0;
    if (__syncthreads_or(match)) return;  // not the chain head (uniform)

    const float mu = fminf(0.4f / 60.0f * (float)(epoch[0] + 1), 1.0f);
    const float omu = 1.0f - mu;

    const size_t rbase = (size_t)y * DIM + t * 4;
    float row[4];
#pragma unroll
    for (int q = 0; q < 4; q++) row[q] = out_em[rbase + q];  // scalar: base 4 mod 16

    for (int j = b; j < BSZ; j++) {
        if (sT[j] != y) continue;  // uniform across block (smem)
        float4 x = *reinterpret_cast<const float4*>(&inputs[(size_t)j * DIM + t * 4]);
        float v0 = mu * row[0] + omu * x.x;
        float v1 = mu * row[1] + omu * x.y;
        float v2 = mu * row[2] + omu * x.z;
        float v3 = mu * row[3] + omu * x.w;
        float sq = v0 * v0 + v1 * v1 + v2 * v2 + v3 * v3;
#pragma unroll
        for (int o = 16; o; o >>= 1) sq += __shfl_xor_sync(~0u, sq, o);
        if (lane == 0) red[warp] = sq;
        __syncthreads();
        if (t == 0) {
            float s = 0.0f;
#pragma unroll
            for (int i = 0; i < 8; i++) s += red[i];
            bc = s;
        }
        __syncthreads();
        float rn = rsqrtf(bc);
        row[0] = v0 * rn; row[1] = v1 * rn; row[2] = v2 * rn; row[3] = v3 * rn;
    }
#pragma unroll
    for (int q = 0; q < 4; q++) out_em[rbase + q] = row[q];
}

// ---------------------------------------------------------------------------
// Entry point. Output layout (float32): [loss(1), ks(128), new_em(32768*1024)]
// ---------------------------------------------------------------------------
extern "C" void kernel_launch(void* const* d_in, const int* in_sizes, int n_in,
                              void* d_out, int out_size) {
    const float* inputs = (const float*)d_in[0];
    const float* em = (const float*)d_in[1];
    const int* targets = (const int*)d_in[2];
    const int* epoch = (const int*)d_in[3];
    float* out = (float*)d_out;
    float* out_em = out + 1 + BSZ;

    static bool attr_set = false;
    if (!attr_set) {
        cudaFuncSetAttribute(gemm_fused_kernel,
                             cudaFuncAttributeMaxDynamicSharedMemorySize, SMEM_DYN);
        attr_set = true;
    }

    gemm_fused_kernel<<<NBLK, NTHREADS, SMEM_DYN>>>(inputs, em, out_em, targets);
    scatter_loss_kernel<<<BSZ + 1, 256>>>(inputs, targets, epoch, out_em, out);
}

// round 16
// speedup vs baseline: 1.3909x; 1.1099x over previous
#include <cuda_runtime.h>
#include <cuda_bf16.h>
#include <cstdint>

#define BSZ 128
#define DIM 1024
#define NCLS 32768
#define INV_TAU 20.0f
#define THRESH 20.0f
#define BN 256
#define NBLK (NCLS / BN)    // 128 gemm blocks (one wave)
#define BK 32               // k per tile (32 fp8 bytes per row)
#define NT (DIM / BK)       // 32 iterations

#define NCONS 512           // 16 consumer warps
#define NTHREADS 640        // + 4 producer warps
#define NSLOT 3

// Scratch (device globals: no allocations allowed)
__device__ alignas(16) uint8_t g_a8[BSZ * DIM];         // e4m3 inputs
// TRANSPOSED partials: [blk][b] -> coalesced writes (gemm) and reads (loss)
__device__ alignas(16) float g_pse[NBLK * BSZ];         // partial sumexp(s-20)
__device__ alignas(16) float g_pcn[NBLK * BSZ];         // partial count > 20
__device__ alignas(16) float g_pss[NBLK * BSZ];         // partial sum of s > 20
__device__ alignas(16) float g_st[BSZ];                 // s[target[b]]

// dynamic smem rings (3 slots each):
//   A fp8   : 128 rows x 48B stride  = 6144/slot   @ 0
//   B fp8   : 256 rows x 48B stride  = 12288/slot  @ 18432
//   B fp32  : 256 rows x 128B        = 32768/slot  @ 55296
#define A_OFF 0
#define B8_OFF 18432
#define BF32_OFF 55296
#define SMEM_DYN 153600
#define RSTRIDE 48

// named barriers: 1+s = FULL(s), 4+s = EMPTY(s)
#define BAR_FULL(s) (1 + (s))
#define BAR_EMPTY(s) (4 + (s))

__device__ __forceinline__ void bar_sync(int id) {
    asm volatile("bar.sync %0, %1;" :: "r"(id), "n"(NTHREADS) : "memory");
}
__device__ __forceinline__ void bar_arrive(int id) {
    asm volatile("bar.arrive %0, %1;" :: "r"(id), "n"(NTHREADS) : "memory");
}
__device__ __forceinline__ unsigned su32(const void* p) {
    return (unsigned)__cvta_generic_to_shared(p);
}
__device__ __forceinline__ uint32_t pack_e4m3x4(float4 v) {
    uint16_t lo, hi;
    asm("cvt.rn.satfinite.e4m3x2.f32 %0, %1, %2;" : "=h"(lo) : "f"(v.y), "f"(v.x));
    asm("cvt.rn.satfinite.e4m3x2.f32 %0, %1, %2;" : "=h"(hi) : "f"(v.w), "f"(v.z));
    return (uint32_t)lo | ((uint32_t)hi << 16);
}
__device__ __forceinline__ void cpasync16(uint32_t dst, const void* src) {
    asm volatile("cp.async.cg.shared.global [%0], [%1], 16;"
                 :: "r"(dst), "l"(src) : "memory");
}
__device__ __forceinline__ void mma_fp8(float* c, const uint32_t* a, const uint32_t* b) {
    asm volatile(
        "mma.sync.aligned.m16n8k32.row.col.f32.e4m3.e4m3.f32 "
        "{%0,%1,%2,%3}, {%4,%5,%6,%7}, {%8,%9}, {%0,%1,%2,%3};\n"
        : "+f"(c[0]), "+f"(c[1]), "+f"(c[2]), "+f"(c[3])
        : "r"(a[0]), "r"(a[1]), "r"(a[2]), "r"(a[3]), "r"(b[0]), "r"(b[1]));
}

// ---------------------------------------------------------------------------
// K0: convert inputs to e4m3 once
// ---------------------------------------------------------------------------
__global__ __launch_bounds__(256) void convert_inputs_kernel(const float* __restrict__ in) {
    int i = (blockIdx.x * 256 + threadIdx.x) * 4;
    float4 v = *reinterpret_cast<const float4*>(&in[i]);
    *reinterpret_cast<uint32_t*>(&g_a8[i]) = pack_e4m3x4(v);
}

// ---------------------------------------------------------------------------
// K1: warp-specialized fp8 GEMM (scores = inputs @ em^T * 20) fused with
// em -> out_em copy and softmax statistics. (R12 base — best known.)
//   warps 0..15  : consumers — ldmatrix + QMMA only (32x64 tile each)
//   warps 16..19 : producers — cp.async rings, out_em copy, fp8 staging
// 3-slot rings; named-barrier full/empty handshake.
// ---------------------------------------------------------------------------
__global__ __launch_bounds__(NTHREADS, 1) void gemm_fused_kernel(
    const float* __restrict__ em,
    float* __restrict__ out_em,
    const int* __restrict__ targets) {
    extern __shared__ char dsm[];
    __shared__ float sRed[3][BSZ][4];
    __shared__ int sT[BSZ];

    const int tid = threadIdx.x;
    const int warp = tid >> 5;
    const int lane = tid & 31;
    const int cBase = blockIdx.x * BN;

    if (tid < BSZ) sT[tid] = targets[tid];
    __syncthreads();

    if (warp >= 16) {
        // =================== PRODUCER ===================
        const int p = tid - NCONS;  // 0..127

        auto issueTile = [&](int t) {
            const int slot = t % NSLOT;
            char* bdst = dsm + BF32_OFF + slot * 32768;
#pragma unroll
            for (int j = 0; j < 16; j++) {
                int c = p + j * 128;          // 0..2047
                int row = c >> 3, q = c & 7;
                cpasync16(su32(bdst + row * 128 + q * 16),
                          (const char*)em +
                              ((size_t)(cBase + row) * DIM + t * BK + q * 4) * 4);
            }
            char* adst = dsm + A_OFF + slot * 6144;
#pragma unroll
            for (int h2 = 0; h2 < 2; h2++) {
                int c = p + h2 * 128;         // 0..255
                int row = c >> 1, h = c & 1;
                cpasync16(su32(adst + row * RSTRIDE + h * 16),
                          (const char*)g_a8 + row * DIM + t * BK + h * 16);
            }
        };

        issueTile(0);
        asm volatile("cp.async.commit_group;" ::: "memory");
        issueTile(1);
        asm volatile("cp.async.commit_group;" ::: "memory");

        for (int kt = 0; kt < NT; kt++) {
            const int t = kt + 2;
            if (t < NT) {
                if (t >= NSLOT) bar_sync(BAR_EMPTY(t % NSLOT));  // slot freed
                issueTile(t);
            }
            asm volatile("cp.async.commit_group;" ::: "memory");
            asm volatile("cp.async.wait_group 2;" ::: "memory");  // tile kt landed

            // ---- stage tile kt: fp32 ring -> out_em copy + fp8 ring ----
            const int slot = kt % NSLOT;
            const char* bsrc = dsm + BF32_OFF + slot * 32768;
            char* b8 = dsm + B8_OFF + slot * 12288;
#pragma unroll
            for (int j = 0; j < 16; j++) {
                int c = p + j * 128;
                int row = c >> 3, q = c & 7;
                float4 v = *reinterpret_cast<const float4*>(bsrc + row * 128 + q * 16);
                size_t gb = (size_t)(cBase + row) * DIM + kt * BK + q * 4;
                __stcs(&out_em[gb], v.x);                              // addr 4 mod 16
                __stcs(reinterpret_cast<float2*>(&out_em[gb + 1]),
                       make_float2(v.y, v.z));                         // addr 8 mod 16
                __stcs(&out_em[gb + 3], v.w);
                *reinterpret_cast<uint32_t*>(b8 + row * RSTRIDE + q * 4) = pack_e4m3x4(v);
            }
            bar_arrive(BAR_FULL(slot));
        }
    } else {
        // =================== CONSUMER ===================
        const int wR = warp & 3;   // M row-group (32 rows)
        const int wC = warp >> 2;  // N col-group (64 cols)

        float acc[2][8][4];
#pragma unroll
        for (int i = 0; i < 2; i++)
#pragma unroll
            for (int j = 0; j < 8; j++)
#pragma unroll
                for (int k = 0; k < 4; k++) acc[i][j][k] = 0.0f;

        const int ar = lane & 15;
        const int ah = (lane >> 4) * 16;
        const int br = lane & 7;
        const int bh = ((lane >> 3) & 1) * 16;

        for (int kt = 0; kt < NT; kt++) {
            const int slot = kt % NSLOT;
            bar_sync(BAR_FULL(slot));
            const char* as = dsm + A_OFF + slot * 6144;
            const char* bs = dsm + B8_OFF + slot * 12288;

            uint32_t afr[2][4];
#pragma unroll
            for (int i = 0; i < 2; i++) {
                unsigned addr = su32(as + (wR * 32 + i * 16 + ar) * RSTRIDE + ah);
                asm volatile(
                    "ldmatrix.sync.aligned.m8n8.x4.shared.b16 {%0,%1,%2,%3}, [%4];"
                    : "=r"(afr[i][0]), "=r"(afr[i][1]), "=r"(afr[i][2]), "=r"(afr[i][3])
                    : "r"(addr));
            }
#pragma unroll
            for (int j = 0; j < 8; j++) {
                uint32_t bfr[2];
                unsigned addr = su32(bs + (wC * 64 + j * 8 + br) * RSTRIDE + bh);
                asm volatile(
                    "ldmatrix.sync.aligned.m8n8.x2.shared.b16 {%0,%1}, [%2];"
                    : "=r"(bfr[0]), "=r"(bfr[1])
                    : "r"(addr));
                mma_fp8(acc[0][j], afr[0], bfr);
                mma_fp8(acc[1][j], afr[1], bfr);
            }
            bar_arrive(BAR_EMPTY(slot));
        }

        // ---- fused epilogue: per-row partial statistics ----
#pragma unroll
        for (int i = 0; i < 2; i++) {
#pragma unroll
            for (int half = 0; half < 2; half++) {
                int bb = wR * 32 + i * 16 + (lane >> 2) + half * 8;  // sample index
                int tgt = sT[bb];
                float se = 0.0f, cn = 0.0f, ss = 0.0f;
#pragma unroll
                for (int j = 0; j < 8; j++) {
                    int cc = cBase + wC * 64 + j * 8 + (lane & 3) * 2;
                    float v0 = acc[i][j][half * 2 + 0] * INV_TAU;
                    float v1 = acc[i][j][half * 2 + 1] * INV_TAU;
                    se += __expf(v0 - 20.0f) + __expf(v1 - 20.0f);
                    if (v0 > THRESH) { cn += 1.0f; ss += v0; }
                    if (v1 > THRESH) { cn += 1.0f; ss += v1; }
                    if (cc == tgt) g_st[bb] = v0;
                    if (cc + 1 == tgt) g_st[bb] = v1;
                }
#pragma unroll
                for (int o = 1; o < 4; o <<= 1) {
                    se += __shfl_xor_sync(~0u, se, o);
                    cn += __shfl_xor_sync(~0u, cn, o);
                    ss += __shfl_xor_sync(~0u, ss, o);
                }
                if ((lane & 3) == 0) {
                    sRed[0][bb][wC] = se;
                    sRed[1][bb][wC] = cn;
                    sRed[2][bb][wC] = ss;
                }
            }
        }
    }

    __syncthreads();
    if (tid < BSZ) {
        // TRANSPOSED, coalesced partial writes: [blk][b]
        g_pse[blockIdx.x * BSZ + tid] =
            sRed[0][tid][0] + sRed[0][tid][1] + sRed[0][tid][2] + sRed[0][tid][3];
        g_pcn[blockIdx.x * BSZ + tid] =
            sRed[1][tid][0] + sRed[1][tid][1] + sRed[1][tid][2] + sRed[1][tid][3];
        g_pss[blockIdx.x * BSZ + tid] =
            sRed[2][tid][0] + sRed[2][tid][1] + sRed[2][tid][2] + sRed[2][tid][3];
    }
}

// ---------------------------------------------------------------------------
// K2: fused scatter + loss.
// Blocks 0..127: EMA scatter chains (O(1) head detection via smem + ballot).
// Block 128: loss — thread b owns sample b; coalesced reduction over the
// transposed partials ([blk][b] layout), then mean.
// ---------------------------------------------------------------------------
__global__ __launch_bounds__(256) void scatter_loss_kernel(const float* __restrict__ inputs,
                                                           const int* __restrict__ targets,
                                                           const int* __restrict__ epoch,
                                                           float* __restrict__ out_em,
                                                           float* __restrict__ out) {
    const int t = threadIdx.x;
    const int warp = t >> 5;
    const int lane = t & 31;

    if (blockIdx.x == BSZ) {
        __shared__ float sLoss[BSZ];
        if (t < BSZ) {
            const int b = t;
            float se = 0.0f, cn = 0.0f, ss = 0.0f;
#pragma unroll 8
            for (int i = 0; i < NBLK; i++) {   // coalesced: lane-contiguous b
                se += g_pse[i * BSZ + b];
                cn += g_pcn[i * BSZ + b];
                ss += g_pss[i * BSZ + b];
            }
            float st = g_st[b];
            float lse = 20.0f + logf(se);
            float logpt = st - lse;
            int n = (int)(cn + 0.5f);
            float loss;
            if (n > 1) {
                float kk = 1.0f / ((float)n * logf((float)n));
                int ta = (st > THRESH) ? 1 : 0;
                float extra = kk * ((ss - (ta ? st : 0.0f)) - (float)(n - ta) * lse);
                loss = -(extra + logpt);
            } else {
                loss = -logpt;
            }
            sLoss[b] = loss;
            out[1 + b] = cn;  // ks
        }
        __syncthreads();
        if (t == 0) {
            float acc = 0.0f;
            for (int i = 0; i < BSZ; i++) acc += sLoss[i];
            out[0] = acc / (float)BSZ;
        }
        return;
    }

    // ---- scatter block ----
    __shared__ int sT[BSZ];
    __shared__ float red[8];
    __shared__ float bc;
    if (t < BSZ) sT[t] = targets[t];
    __syncthreads();

    const int b = blockIdx.x;
    const int y = sT[b];
    int match = (t < b && sT[t] == y) ? 1 : 0;
    if (__syncthreads_or(match)) return;  // not the chain head (uniform)

    const float mu = fminf(0.4f / 60.0f * (float)(epoch[0] + 1), 1.0f);
    const float omu = 1.0f - mu;

    const size_t rbase = (size_t)y * DIM + t * 4;
    float row[4];
#pragma unroll
    for (int q = 0; q < 4; q++) row[q] = out_em[rbase + q];  // scalar: base 4 mod 16

    for (int j = b; j < BSZ; j++) {
        if (sT[j] != y) continue;  // uniform across block (smem)
        float4 x = *reinterpret_cast<const float4*>(&inputs[(size_t)j * DIM + t * 4]);
        float v0 = mu * row[0] + omu * x.x;
        float v1 = mu * row[1] + omu * x.y;
        float v2 = mu * row[2] + omu * x.z;
        float v3 = mu * row[3] + omu * x.w;
        float sq = v0 * v0 + v1 * v1 + v2 * v2 + v3 * v3;
#pragma unroll
        for (int o = 16; o; o >>= 1) sq += __shfl_xor_sync(~0u, sq, o);
        if (lane == 0) red[warp] = sq;
        __syncthreads();
        if (t == 0) {
            float s = 0.0f;
#pragma unroll
            for (int i = 0; i < 8; i++) s += red[i];
            bc = s;
        }
        __syncthreads();
        float rn = rsqrtf(bc);
        row[0] = v0 * rn; row[1] = v1 * rn; row[2] = v2 * rn; row[3] = v3 * rn;
    }
#pragma unroll
    for (int q = 0; q < 4; q++) out_em[rbase + q] = row[q];
}

// ---------------------------------------------------------------------------
// Entry point. Output layout (float32): [loss(1), ks(128), new_em(32768*1024)]
// ---------------------------------------------------------------------------
extern "C" void kernel_launch(void* const* d_in, const int* in_sizes, int n_in,
                              void* d_out, int out_size) {
    const float* inputs = (const float*)d_in[0];
    const float* em = (const float*)d_in[1];
    const int* targets = (const int*)d_in[2];
    const int* epoch = (const int*)d_in[3];
    float* out = (float*)d_out;
    float* out_em = out + 1 + BSZ;

    static bool attr_set = false;
    if (!attr_set) {
        cudaFuncSetAttribute(gemm_fused_kernel,
                             cudaFuncAttributeMaxDynamicSharedMemorySize, SMEM_DYN);
        attr_set = true;
    }

    convert_inputs_kernel<<<128, 256>>>(inputs);
    gemm_fused_kernel<<<NBLK, NTHREADS, SMEM_DYN>>>(em, out_em, targets);
    scatter_loss_kernel<<<BSZ + 1, 256>>>(inputs, targets, epoch, out_em, out);
}